// round 9
// baseline (speedup 1.0000x reference)
#include <cuda_runtime.h>
#include <cuda_bf16.h>
#include <cstdint>
#include <math.h>

#define BATCH 4
#define DIM   128
#define NPTS  4096
#define NB    (BATCH*NPTS)
#define MC    64            // m-chunks
#define MPER  64            // m per chunk
#define NBLK  (MC*BATCH)    // 256
#define INV_T 14.285714285714286f
#define FRB   16            // frobenius blocks per batch in k_redB

// bf16 tile row stride: 64 m + 8 pad = 72 bf16 = 144 B (conflict-free LDSM)
#define BSTRIDE 144

// ---- device scratch (no allocations allowed) ----
__device__ uint32_t g_gpart[4194304];      // bf16x2 gram partials, 16.8 MB
__device__ float g_gsum[8*16384];          // fp32 gram sums, 512 KB
__device__ float g_spart[2*BATCH*MC*DIM];  // per-d column-sum partials
__device__ float g_dgpart[NBLK];
__device__ float g_dg2part[NBLK];
__device__ float g_fpart[BATCH*FRB];
__device__ float g_s1[BATCH];
__device__ unsigned int g_ctr;             // zero-init; reset by finisher

// =============================== PTX helpers ===============================
__device__ __forceinline__ uint32_t smem_u32(const void* p) {
    uint32_t a;
    asm("{ .reg .u64 t; cvta.to.shared.u64 t, %1; cvt.u32.u64 %0, t; }"
        : "=r"(a) : "l"(p));
    return a;
}
__device__ __forceinline__ void ldsm_x4(uint32_t* r, uint32_t addr) {
    asm volatile("ldmatrix.sync.aligned.m8n8.x4.shared.b16 {%0,%1,%2,%3}, [%4];"
        : "=r"(r[0]), "=r"(r[1]), "=r"(r[2]), "=r"(r[3]) : "r"(addr));
}
__device__ __forceinline__ void mma_bf16(float* c, const uint32_t* a,
                                         uint32_t b0, uint32_t b1) {
    asm volatile("mma.sync.aligned.m16n8k16.row.col.f32.bf16.bf16.f32 "
        "{%0,%1,%2,%3}, {%4,%5,%6,%7}, {%8,%9}, {%0,%1,%2,%3};"
        : "+f"(c[0]), "+f"(c[1]), "+f"(c[2]), "+f"(c[3])
        : "r"(a[0]), "r"(a[1]), "r"(a[2]), "r"(a[3]), "r"(b0), "r"(b1));
}
__device__ __forceinline__ uint32_t hmul2u(uint32_t a, uint32_t b) {
    uint32_t r;
    asm("mul.bf16x2 %0, %1, %2;" : "=r"(r) : "r"(a), "r"(b));
    return r;
}
__device__ __forceinline__ uint32_t bf2u(__nv_bfloat162 v) {
    return *(uint32_t*)&v;
}
// bf16x2 unpack as fp32 via pure bit ops (bf16 -> fp32 is a 16-bit shift)
__device__ __forceinline__ float blo(uint32_t u) { return __uint_as_float(u << 16); }
__device__ __forceinline__ float bhi(uint32_t u) { return __uint_as_float(u & 0xffff0000u); }

// smem byte layout (total 37952 B; scratch rq/rk/rd ALIASES the tile region —
// scratch is dead before phase 3 writes the tiles)
#define SB_QB   0            // 18432
#define SB_KB   18432        // 18432  (tiles end at 36864)
#define SB_RQ   0            // alias: 32 dgroups x 64 m x 4B = 8192
#define SB_RK   8192
#define SB_RD   16384        // ends 24576 < 36864 ok
#define SB_NS   36864        // nsum 3*64*4 = 768
#define SB_IQ2  37632        // 32 u32
#define SB_IK2  37760        // 32 u32
#define SB_SCR  37888        // 16 floats
#define SB_TOTAL 37952

// ===========================================================================
// k_main: 512 thr, grid (64,4). UNCHANGED from R6/R8 (proven fast + exact).
// ===========================================================================
__global__ __launch_bounds__(512, 2) void k_main(const float* __restrict__ q,
                                                 const float* __restrict__ k) {
    extern __shared__ char smc[];
    char*  qb  = smc + SB_QB;
    char*  kb  = smc + SB_KB;
    float* rq  = (float*)(smc + SB_RQ);
    float* rk  = (float*)(smc + SB_RK);
    float* rd  = (float*)(smc + SB_RD);
    float* ns  = (float*)(smc + SB_NS);
    uint32_t* iq2 = (uint32_t*)(smc + SB_IQ2);
    uint32_t* ik2 = (uint32_t*)(smc + SB_IK2);
    float* scr = (float*)(smc + SB_SCR);

    int tid = threadIdx.x, wid = tid >> 5, lane = tid & 31;
    int cblk = blockIdx.x, b = blockIdx.y;
    int m0 = cblk * MPER;
    int mgrp = tid & 15, dg0 = tid >> 4;   // dg0 0..31
    int m4 = mgrp * 4;

    // ---- phase 1: single global read; norm/dot partials; raw bf16 in regs
    const float* qg = q + (size_t)b * DIM * NPTS + m0 + m4;
    const float* kg = k + (size_t)b * DIM * NPTS + m0 + m4;
    uint2 qr[4], kr[4];
    float sq0 = 0.f, sq1 = 0.f, sq2 = 0.f, sq3 = 0.f;
    float sk0 = 0.f, sk1 = 0.f, sk2 = 0.f, sk3 = 0.f;
    float dt0 = 0.f, dt1 = 0.f, dt2 = 0.f, dt3 = 0.f;
#pragma unroll
    for (int it = 0; it < 4; it++) {
        int d = dg0 + it * 32;
        float4 vq = *(const float4*)(qg + (size_t)d * NPTS);
        float4 vk = *(const float4*)(kg + (size_t)d * NPTS);
        sq0 += fabsf(vq.x); sq1 += fabsf(vq.y); sq2 += fabsf(vq.z); sq3 += fabsf(vq.w);
        sk0 += fabsf(vk.x); sk1 += fabsf(vk.y); sk2 += fabsf(vk.z); sk3 += fabsf(vk.w);
        dt0 += vq.x * vk.x; dt1 += vq.y * vk.y; dt2 += vq.z * vk.z; dt3 += vq.w * vk.w;
        qr[it] = make_uint2(bf2u(__float22bfloat162_rn(make_float2(vq.x, vq.y))),
                            bf2u(__float22bfloat162_rn(make_float2(vq.z, vq.w))));
        kr[it] = make_uint2(bf2u(__float22bfloat162_rn(make_float2(vk.x, vk.y))),
                            bf2u(__float22bfloat162_rn(make_float2(vk.z, vk.w))));
    }
    *(float4*)(rq + dg0 * 64 + m4) = make_float4(sq0, sq1, sq2, sq3);
    *(float4*)(rk + dg0 * 64 + m4) = make_float4(sk0, sk1, sk2, sk3);
    *(float4*)(rd + dg0 * 64 + m4) = make_float4(dt0, dt1, dt2, dt3);
    __syncthreads();

    // ---- phase 2a: reduce 32 dgroups for each of 64 m; 3 arrays in parallel
    if (tid < 192) {
        int arr = tid >> 6, m = tid & 63;
        const float* basep = (const float*)(smc + arr * 8192);
        float s = 0.f;
#pragma unroll
        for (int g = 0; g < 32; g++) s += basep[g * 64 + m];
        ns[arr * 64 + m] = s;
    }
    __syncthreads();

    // ---- phase 2b: inv norms, packed bf16x2 scales, dg/dg2 block totals ---
    if (tid < 64) {
        int m = tid;
        float iqv = 1.f / fmaxf(ns[m], 1e-12f);
        float ikv = 1.f / fmaxf(ns[64 + m], 1e-12f);
        float dt  = ns[128 + m];
        float iqh = __shfl_down_sync(0xffffffffu, iqv, 1);
        float ikh = __shfl_down_sync(0xffffffffu, ikv, 1);
        if ((m & 1) == 0) {
            iq2[m >> 1] = bf2u(__float22bfloat162_rn(make_float2(iqv, iqh)));
            ik2[m >> 1] = bf2u(__float22bfloat162_rn(make_float2(ikv, ikh)));
        }
        float dg = dt * iqv * ikv;
        float dg2 = dg * dg;
#pragma unroll
        for (int o = 16; o; o >>= 1) {
            dg  += __shfl_down_sync(0xffffffffu, dg, o);
            dg2 += __shfl_down_sync(0xffffffffu, dg2, o);
        }
        if (lane == 0) { scr[wid] = dg; scr[2 + wid] = dg2; }
    }
    __syncthreads();
    if (tid == 0) {
        int blk = b * MC + cblk;
        g_dgpart[blk]  = scr[0] + scr[1];
        g_dg2part[blk] = scr[2] + scr[3];
    }

    // ---- phase 3: HMUL2 normalize regs -> tiles; per-d column sums --------
    float* sqout = g_spart + ((size_t)(0 * BATCH + b) * MC + cblk) * DIM;
    float* skout = g_spart + ((size_t)(1 * BATCH + b) * MC + cblk) * DIM;
    {
        uint32_t su0 = iq2[mgrp * 2], su1 = iq2[mgrp * 2 + 1];
        uint32_t tu0 = ik2[mgrp * 2], tu1 = ik2[mgrp * 2 + 1];
#pragma unroll
        for (int it = 0; it < 4; it++) {
            int d = dg0 + it * 32;
            uint32_t q0 = hmul2u(qr[it].x, su0);
            uint32_t q1 = hmul2u(qr[it].y, su1);
            uint32_t k0 = hmul2u(kr[it].x, tu0);
            uint32_t k1 = hmul2u(kr[it].y, tu1);
            uint32_t off = (uint32_t)(d * BSTRIDE + mgrp * 8);
            *(uint2*)(qb + off) = make_uint2(q0, q1);
            *(uint2*)(kb + off) = make_uint2(k0, k1);
            float cs = (blo(q0) + bhi(q0)) + (blo(q1) + bhi(q1));
            float ck = (blo(k0) + bhi(k0)) + (blo(k1) + bhi(k1));
#pragma unroll
            for (int o = 8; o; o >>= 1) {
                cs += __shfl_down_sync(0xffffffffu, cs, o, 16);
                ck += __shfl_down_sync(0xffffffffu, ck, o, 16);
            }
            if (mgrp == 0) { sqout[d] = cs; skout[d] = ck; }
        }
    }
    __syncthreads();

    // ---- phase 4: two 16x64 gram jobs per warp (gram 0 then gram 1) -------
    int ri = wid >> 1, jc = wid & 1;
    int grp = lane >> 3;
    uint32_t arow_off = (uint32_t)((ri * 16 + ((grp & 1) << 3) + (lane & 7)) * BSTRIDE
                                   + ((grp >> 1) << 4));
    uint32_t brow_off = (uint32_t)((jc * 64 + ((grp >> 1) << 3) + (lane & 7)) * BSTRIDE
                                   + ((grp & 1) << 4));
    int r  = lane >> 2;
    int cp = (lane & 3) << 1;
    int d1r = ri * 16 + r;

#pragma unroll
    for (int gram = 0; gram < 2; gram++) {
        uint32_t base = smem_u32(gram ? kb : qb);
        float c[32];
#pragma unroll
        for (int i = 0; i < 32; i++) c[i] = 0.f;
#pragma unroll
        for (int ks = 0; ks < 4; ks++) {
            uint32_t a[4];
            ldsm_x4(a, base + arow_off + ks * 32);
#pragma unroll
            for (int bt = 0; bt < 4; bt++) {
                uint32_t bb[4];
                ldsm_x4(bb, base + brow_off + (uint32_t)(bt * 16 * BSTRIDE) + ks * 32);
                mma_bf16(c + bt * 8,     a, bb[0], bb[1]);
                mma_bf16(c + bt * 8 + 4, a, bb[2], bb[3]);
            }
        }
        uint32_t* outp = g_gpart
            + ((size_t)(gram * BATCH + b) * MC + cblk) * 8192;  // u32 pairs
#pragma unroll
        for (int bt = 0; bt < 4; bt++) {
#pragma unroll
            for (int h = 0; h < 2; h++) {
                int col = jc * 64 + bt * 16 + h * 8 + cp;
                const float* cc = c + bt * 8 + h * 4;
                outp[(d1r * 128 + col) >> 1] =
                    bf2u(__float22bfloat162_rn(make_float2(cc[0], cc[1])));
                outp[((d1r + 8) * 128 + col) >> 1] =
                    bf2u(__float22bfloat162_rn(make_float2(cc[2], cc[3])));
            }
        }
    }
}

// ===========================================================================
// k_redA: grid (64, 8), 256 thr. Chunk-sum of gram partials -> fp32 g_gsum.
// Thread = (32 positions) x (8 csplits); each thread does 8 INDEPENDENT
// uint4 loads (tree-summed) so all batch in the LSU -> max MLP.
// ===========================================================================
__global__ __launch_bounds__(256) void k_redA() {
    __shared__ float smQ[256][8];
    int tid = threadIdx.x;
    int gb = blockIdx.y;                       // gram*BATCH+b, 0..7
    int pos = blockIdx.x * 32 + (tid & 31);    // uint4 position 0..2047
    int cs = tid >> 5;                         // csplit 0..7

    const uint4* p = (const uint4*)g_gpart + (size_t)gb * MC * 2048
                   + pos + (size_t)cs * 8 * 2048;
    // 8 independent loads
    uint4 u0 = p[0];
    uint4 u1 = p[1 * 2048];
    uint4 u2 = p[2 * 2048];
    uint4 u3 = p[3 * 2048];
    uint4 u4 = p[4 * 2048];
    uint4 u5 = p[5 * 2048];
    uint4 u6 = p[6 * 2048];
    uint4 u7 = p[7 * 2048];

    float a[8];
    a[0] = ((blo(u0.x) + blo(u1.x)) + (blo(u2.x) + blo(u3.x)))
         + ((blo(u4.x) + blo(u5.x)) + (blo(u6.x) + blo(u7.x)));
    a[1] = ((bhi(u0.x) + bhi(u1.x)) + (bhi(u2.x) + bhi(u3.x)))
         + ((bhi(u4.x) + bhi(u5.x)) + (bhi(u6.x) + bhi(u7.x)));
    a[2] = ((blo(u0.y) + blo(u1.y)) + (blo(u2.y) + blo(u3.y)))
         + ((blo(u4.y) + blo(u5.y)) + (blo(u6.y) + blo(u7.y)));
    a[3] = ((bhi(u0.y) + bhi(u1.y)) + (bhi(u2.y) + bhi(u3.y)))
         + ((bhi(u4.y) + bhi(u5.y)) + (bhi(u6.y) + bhi(u7.y)));
    a[4] = ((blo(u0.z) + blo(u1.z)) + (blo(u2.z) + blo(u3.z)))
         + ((blo(u4.z) + blo(u5.z)) + (blo(u6.z) + blo(u7.z)));
    a[5] = ((bhi(u0.z) + bhi(u1.z)) + (bhi(u2.z) + bhi(u3.z)))
         + ((bhi(u4.z) + bhi(u5.z)) + (bhi(u6.z) + bhi(u7.z)));
    a[6] = ((blo(u0.w) + blo(u1.w)) + (blo(u2.w) + blo(u3.w)))
         + ((blo(u4.w) + blo(u5.w)) + (blo(u6.w) + blo(u7.w)));
    a[7] = ((bhi(u0.w) + bhi(u1.w)) + (bhi(u2.w) + bhi(u3.w)))
         + ((bhi(u4.w) + bhi(u5.w)) + (bhi(u6.w) + bhi(u7.w)));

    int slot = cs * 32 + (tid & 31);
#pragma unroll
    for (int i = 0; i < 8; i++) smQ[slot][i] = a[i];
    __syncthreads();

    // combine the 8 csplits in fixed order; write coalesced fp32
    int lp = tid >> 3, e = tid & 7;            // local pos 0..31, elem 0..7
    float s = ((smQ[lp][e] + smQ[32 + lp][e])
             + (smQ[64 + lp][e] + smQ[96 + lp][e]))
            + ((smQ[128 + lp][e] + smQ[160 + lp][e])
             + (smQ[192 + lp][e] + smQ[224 + lp][e]));
    g_gsum[(size_t)gb * 16384 + (size_t)(blockIdx.x * 32 + lp) * 8 + e] = s;
}

// ===========================================================================
// k_redB: grid (FRB+1, 4), 256 thr. x<FRB: frobenius over fp32 g_gsum
// (float4 loads). x==FRB: s1. Last arriving block computes the final loss.
// ===========================================================================
__global__ __launch_bounds__(256) void k_redB(float* __restrict__ out) {
    __shared__ float rr[8];
    __shared__ float sqs[DIM], sks[DIM];
    __shared__ bool last;
    int b = blockIdx.y;
    int tid = threadIdx.x;

    if (blockIdx.x < FRB) {
        int idx = blockIdx.x * 1024 + tid * 4;    // 0..16383
        const float4* pq = (const float4*)(g_gsum + (size_t)(0 * BATCH + b) * 16384 + idx);
        const float4* pk = (const float4*)(g_gsum + (size_t)(1 * BATCH + b) * 16384 + idx);
        float4 gq = *pq;
        float4 gk = *pk;
        float f = (gq.x * gk.x + gq.y * gk.y) + (gq.z * gk.z + gq.w * gk.w);
#pragma unroll
        for (int o = 16; o; o >>= 1) f += __shfl_down_sync(0xffffffffu, f, o);
        if ((tid & 31) == 0) rr[tid >> 5] = f;
        __syncthreads();
        if (tid == 0) {
            float t = 0.f;
#pragma unroll
            for (int i = 0; i < 8; i++) t += rr[i];
            g_fpart[b * FRB + blockIdx.x] = t;
        }
    } else {
        int w = tid >> 7, d = tid & 127;
        const float* p = g_spart + ((size_t)(w * BATCH + b) * MC) * DIM + d;
        float s = 0.f;
#pragma unroll 8
        for (int c = 0; c < MC; c++) s += p[(size_t)c * DIM];
        if (w == 0) sqs[d] = s; else sks[d] = s;
        __syncthreads();
        if (tid < 128) {
            float v = sqs[tid] * sks[tid];
#pragma unroll
            for (int o = 16; o; o >>= 1) v += __shfl_down_sync(0xffffffffu, v, o);
            if ((tid & 31) == 0) rr[tid >> 5] = v;
        }
        __syncthreads();
        if (tid == 0) g_s1[b] = rr[0] + rr[1] + rr[2] + rr[3];
    }

    // ---- finisher: last of the (FRB+1)*BATCH blocks computes the loss -----
    __syncthreads();
    if (tid == 0) {
        __threadfence();
        last = (atomicAdd(&g_ctr, 1u) == (FRB + 1) * BATCH - 1);
    }
    __syncthreads();
    if (last) {
        __shared__ float red[256];
        const float halfT2 = 0.5f * INV_T * INV_T;
        float v = 0.f;
        if (tid < BATCH * FRB) v += halfT2 * g_fpart[tid];
        if (tid < BATCH)       v += INV_T * g_s1[tid];
        v -= INV_T * g_dgpart[tid] + halfT2 * g_dg2part[tid];   // NBLK==256
        red[tid] = v;
        __syncthreads();
#pragma unroll
        for (int s = 128; s; s >>= 1) {
            if (tid < s) red[tid] += red[tid + s];
            __syncthreads();
        }
        if (tid == 0) {
            out[0] = logf((float)NPTS) + red[0] / ((float)NPTS * (float)NB);
            g_ctr = 0;   // reset for next graph replay
        }
    }
}

// ===========================================================================
extern "C" void kernel_launch(void* const* d_in, const int* in_sizes, int n_in,
                              void* d_out, int out_size) {
    const float* q = (const float*)d_in[0];
    const float* k = (const float*)d_in[1];
    float* out = (float*)d_out;
    (void)in_sizes; (void)n_in; (void)out_size;

    cudaFuncSetAttribute(k_main, cudaFuncAttributeMaxDynamicSharedMemorySize,
                         SB_TOTAL);

    k_main<<<dim3(MC, BATCH), 512, SB_TOTAL>>>(q, k);
    k_redA<<<dim3(64, 8), 256>>>();
    k_redB<<<dim3(FRB + 1, BATCH), 256>>>(out);
}

// round 10
// speedup vs baseline: 1.1890x; 1.1890x over previous
#include <cuda_runtime.h>
#include <cuda_bf16.h>
#include <cuda_fp8.h>
#include <cstdint>
#include <math.h>

#define BATCH 4
#define DIM   128
#define NPTS  4096
#define NB    (BATCH*NPTS)
#define MC    32            // m-chunks
#define MPER  128           // m per chunk
#define NBLK  (MC*BATCH)    // 128
#define INV_T 14.285714285714286f
#define FRB   16            // frobenius blocks per batch in k_redB
#define QS    64.0f         // fp8 pre-scale (folded out in finisher)
#define QS4   16777216.0f   // 64^4
#define QS2   4096.0f       // 64^2

// fp8 tile: [128 d rows][128 m + 16 pad] = 144 B row stride (conflict-free LDSM)
#define TSTRIDE 144

// ---- device scratch (no allocations allowed) ----
__device__ uint32_t g_gpart[2097152];      // bf16x2 gram partials, 8.4 MB
__device__ float g_gsum[8*16384];          // fp32 gram sums, 512 KB
__device__ float g_spart[2*BATCH*MC*DIM];  // per-d column-sum partials (x64 scaled)
__device__ float g_dgpart[NBLK];
__device__ float g_dg2part[NBLK];
__device__ float g_fpart[BATCH*FRB];
__device__ float g_s1[BATCH];
__device__ unsigned int g_ctr;             // zero-init; reset by finisher

// =============================== PTX helpers ===============================
__device__ __forceinline__ uint32_t smem_u32(const void* p) {
    uint32_t a;
    asm("{ .reg .u64 t; cvta.to.shared.u64 t, %1; cvt.u32.u64 %0, t; }"
        : "=r"(a) : "l"(p));
    return a;
}
__device__ __forceinline__ void ldsm_x4(uint32_t* r, uint32_t addr) {
    asm volatile("ldmatrix.sync.aligned.m8n8.x4.shared.b16 {%0,%1,%2,%3}, [%4];"
        : "=r"(r[0]), "=r"(r[1]), "=r"(r[2]), "=r"(r[3]) : "r"(addr));
}
__device__ __forceinline__ void mma_fp8(float* c, const uint32_t* a,
                                        uint32_t b0, uint32_t b1) {
    asm volatile("mma.sync.aligned.m16n8k32.row.col.f32.e4m3.e4m3.f32 "
        "{%0,%1,%2,%3}, {%4,%5,%6,%7}, {%8,%9}, {%0,%1,%2,%3};"
        : "+f"(c[0]), "+f"(c[1]), "+f"(c[2]), "+f"(c[3])
        : "r"(a[0]), "r"(a[1]), "r"(a[2]), "r"(a[3]), "r"(b0), "r"(b1));
}
__device__ __forceinline__ uint32_t bf2u(__nv_bfloat162 v) {
    return *(uint32_t*)&v;
}
// bf16x2 unpack as fp32 via pure bit ops
__device__ __forceinline__ float blo(uint32_t u) { return __uint_as_float(u << 16); }
__device__ __forceinline__ float bhi(uint32_t u) { return __uint_as_float(u & 0xffff0000u); }
__device__ __forceinline__ uint32_t pack_fp8x4(float a, float b, float c, float d) {
    __nv_fp8x2_storage_t lo =
        __nv_cvt_float2_to_fp8x2(make_float2(a, b), __NV_SATFINITE, __NV_E4M3);
    __nv_fp8x2_storage_t hi =
        __nv_cvt_float2_to_fp8x2(make_float2(c, d), __NV_SATFINITE, __NV_E4M3);
    return (uint32_t)lo | ((uint32_t)hi << 16);
}

// smem byte layout (scratch rq/rk/rd aliases the tile region — dead by phase 3)
#define SB_QB   0            // 18432
#define SB_KB   18432        // -> 36864
#define SB_RQ   0            // alias: 16 warps x 128 m x 4B = 8192
#define SB_RK   8192
#define SB_RD   16384        // ends 24576 < 36864 ok
#define SB_IQ   36864        // 128 f (x64-scaled inv norms)
#define SB_IK   37376
#define SB_SCR  37888        // 16 floats
#define SB_TOTAL 37952

// ===========================================================================
// k_main: 512 thr, grid (32,4) — R5 skeleton with FP8 tiles + fp8 mma.
// ===========================================================================
__global__ __launch_bounds__(512, 1) void k_main(const float* __restrict__ q,
                                                 const float* __restrict__ k) {
    extern __shared__ char smc[];
    char*  qb  = smc + SB_QB;
    char*  kb  = smc + SB_KB;
    float* rq  = (float*)(smc + SB_RQ);
    float* rk  = (float*)(smc + SB_RK);
    float* rd  = (float*)(smc + SB_RD);
    float* iq  = (float*)(smc + SB_IQ);
    float* ik  = (float*)(smc + SB_IK);
    float* scr = (float*)(smc + SB_SCR);

    int tid = threadIdx.x, wid = tid >> 5, lane = tid & 31;
    int cblk = blockIdx.x, b = blockIdx.y;
    int m0 = cblk * MPER;
    int m4 = lane * 4;

    // ---- phase 1: single global read; norm/dot partials; raw bf16 in regs
    const float* qg = q + (size_t)b * DIM * NPTS + m0 + m4;
    const float* kg = k + (size_t)b * DIM * NPTS + m0 + m4;
    uint2 qr[8], kr[8];
    float sq0 = 0.f, sq1 = 0.f, sq2 = 0.f, sq3 = 0.f;
    float sk0 = 0.f, sk1 = 0.f, sk2 = 0.f, sk3 = 0.f;
    float dt0 = 0.f, dt1 = 0.f, dt2 = 0.f, dt3 = 0.f;
#pragma unroll
    for (int it = 0; it < 8; it++) {
        int d = it * 16 + wid;
        float4 vq = *(const float4*)(qg + (size_t)d * NPTS);
        float4 vk = *(const float4*)(kg + (size_t)d * NPTS);
        sq0 += fabsf(vq.x); sq1 += fabsf(vq.y); sq2 += fabsf(vq.z); sq3 += fabsf(vq.w);
        sk0 += fabsf(vk.x); sk1 += fabsf(vk.y); sk2 += fabsf(vk.z); sk3 += fabsf(vk.w);
        dt0 += vq.x * vk.x; dt1 += vq.y * vk.y; dt2 += vq.z * vk.z; dt3 += vq.w * vk.w;
        qr[it] = make_uint2(bf2u(__float22bfloat162_rn(make_float2(vq.x, vq.y))),
                            bf2u(__float22bfloat162_rn(make_float2(vq.z, vq.w))));
        kr[it] = make_uint2(bf2u(__float22bfloat162_rn(make_float2(vk.x, vk.y))),
                            bf2u(__float22bfloat162_rn(make_float2(vk.z, vk.w))));
    }
    *(float4*)(rq + wid * 128 + m4) = make_float4(sq0, sq1, sq2, sq3);
    *(float4*)(rk + wid * 128 + m4) = make_float4(sk0, sk1, sk2, sk3);
    *(float4*)(rd + wid * 128 + m4) = make_float4(dt0, dt1, dt2, dt3);
    __syncthreads();

    // ---- phase 2: reduce over 16 warps; inv norms (x64 for fp8); dg/dg2 ---
    if (tid < 128) {
        float sq = 0.f, sk = 0.f, dt = 0.f;
#pragma unroll
        for (int w = 0; w < 16; w++) {
            sq += rq[w * 128 + tid];
            sk += rk[w * 128 + tid];
            dt += rd[w * 128 + tid];
        }
        float iqv = 1.f / fmaxf(sq, 1e-12f);
        float ikv = 1.f / fmaxf(sk, 1e-12f);
        iq[tid] = iqv * QS;
        ik[tid] = ikv * QS;
        float dg = dt * iqv * ikv;          // exact fp32, unscaled
        float dg2 = dg * dg;
#pragma unroll
        for (int o = 16; o; o >>= 1) {
            dg  += __shfl_down_sync(0xffffffffu, dg, o);
            dg2 += __shfl_down_sync(0xffffffffu, dg2, o);
        }
        if (lane == 0) { scr[wid] = dg; scr[4 + wid] = dg2; }
    }
    __syncthreads();
    if (tid == 0) {
        int blk = b * MC + cblk;
        g_dgpart[blk]  = scr[0] + scr[1] + scr[2] + scr[3];
        g_dg2part[blk] = scr[4] + scr[5] + scr[6] + scr[7];
    }

    // ---- phase 3: normalize (fp32) -> fp8 tiles; per-d column sums --------
    float* sqout = g_spart + ((size_t)(0 * BATCH + b) * MC + cblk) * DIM;
    float* skout = g_spart + ((size_t)(1 * BATCH + b) * MC + cblk) * DIM;
    {
        float4 iqv = *(float4*)(iq + m4);
        float4 ikv = *(float4*)(ik + m4);
#pragma unroll
        for (int it = 0; it < 8; it++) {
            int d = it * 16 + wid;
            float x0 = blo(qr[it].x) * iqv.x, x1 = bhi(qr[it].x) * iqv.y;
            float x2 = blo(qr[it].y) * iqv.z, x3 = bhi(qr[it].y) * iqv.w;
            float y0 = blo(kr[it].x) * ikv.x, y1 = bhi(kr[it].x) * ikv.y;
            float y2 = blo(kr[it].y) * ikv.z, y3 = bhi(kr[it].y) * ikv.w;
            uint32_t off = (uint32_t)(d * TSTRIDE) + (uint32_t)m4;
            *(uint32_t*)(qb + off) = pack_fp8x4(x0, x1, x2, x3);
            *(uint32_t*)(kb + off) = pack_fp8x4(y0, y1, y2, y3);
            float cs = (x0 + x1) + (x2 + x3);   // x64 scaled; fixed in finisher
            float ck = (y0 + y1) + (y2 + y3);
#pragma unroll
            for (int o = 16; o; o >>= 1) {
                cs += __shfl_down_sync(0xffffffffu, cs, o);
                ck += __shfl_down_sync(0xffffffffu, ck, o);
            }
            if (lane == 0) { sqout[d] = cs; skout[d] = ck; }
        }
    }
    __syncthreads();

    // ---- phase 4: fp8 grams. warps 0-7 -> Gq, 8-15 -> Gk -----------------
    // A row-major [d1][m], B col-major [m][d2] share the [d][m] fp8 tile.
    int which = wid >> 3;
    int wrow = wid & 7;
    uint32_t base = smem_u32(which ? kb : qb);
    int grp = lane >> 3;
    uint32_t arow_off = (uint32_t)((wrow * 16 + ((grp & 1) << 3) + (lane & 7)) * TSTRIDE
                                   + ((grp >> 1) << 4));
    uint32_t brow_off = (uint32_t)((((grp & 1) << 3) + (lane & 7)) * TSTRIDE
                                   + ((grp >> 1) << 4));
    int r  = lane >> 2;
    int cp = (lane & 3) << 1;
    int d1r = wrow * 16 + r;

    float c[64];
#pragma unroll
    for (int i = 0; i < 64; i++) c[i] = 0.f;

#pragma unroll
    for (int ks = 0; ks < 4; ks++) {           // K=32 fp8 per mma, 4*32=128 m
        uint32_t a[4];
        ldsm_x4(a, base + arow_off + ks * 32);
#pragma unroll
        for (int bt = 0; bt < 8; bt++) {
            uint32_t bb[4];
            ldsm_x4(bb, base + brow_off + (uint32_t)(bt * 16 * TSTRIDE) + ks * 32);
            mma_fp8(c + bt * 8,     a, bb[0], bb[2]);
            mma_fp8(c + bt * 8 + 4, a, bb[1], bb[3]);
        }
    }

    uint32_t* outp = g_gpart
        + ((size_t)(which * BATCH + b) * MC + cblk) * 8192;   // bf16-pair tile
#pragma unroll
    for (int bt = 0; bt < 8; bt++) {
#pragma unroll
        for (int h = 0; h < 2; h++) {
            int col = bt * 16 + h * 8 + cp;
            const float* cc = c + bt * 8 + h * 4;
            outp[(d1r * 128 + col) >> 1] =
                bf2u(__float22bfloat162_rn(make_float2(cc[0], cc[1])));
            outp[((d1r + 8) * 128 + col) >> 1] =
                bf2u(__float22bfloat162_rn(make_float2(cc[2], cc[3])));
        }
    }
}

// ===========================================================================
// k_redA: grid (64, 8), 256 thr. Chunk-sum bf16 gram partials -> fp32 g_gsum.
// Thread = (32 positions) x (8 csplits of 4 chunks): 4 independent uint4
// loads per thread -> max MLP.
// ===========================================================================
__global__ __launch_bounds__(256) void k_redA() {
    __shared__ float smQ[256][8];
    int tid = threadIdx.x;
    int gb = blockIdx.y;                       // gram*BATCH+b, 0..7
    int pos = blockIdx.x * 32 + (tid & 31);    // uint4 position 0..2047
    int cs = tid >> 5;                         // csplit 0..7 (4 chunks each)

    const uint4* p = (const uint4*)g_gpart + (size_t)gb * MC * 2048
                   + pos + (size_t)cs * 4 * 2048;
    uint4 u0 = p[0];
    uint4 u1 = p[1 * 2048];
    uint4 u2 = p[2 * 2048];
    uint4 u3 = p[3 * 2048];

    float a[8];
    a[0] = (blo(u0.x) + blo(u1.x)) + (blo(u2.x) + blo(u3.x));
    a[1] = (bhi(u0.x) + bhi(u1.x)) + (bhi(u2.x) + bhi(u3.x));
    a[2] = (blo(u0.y) + blo(u1.y)) + (blo(u2.y) + blo(u3.y));
    a[3] = (bhi(u0.y) + bhi(u1.y)) + (bhi(u2.y) + bhi(u3.y));
    a[4] = (blo(u0.z) + blo(u1.z)) + (blo(u2.z) + blo(u3.z));
    a[5] = (bhi(u0.z) + bhi(u1.z)) + (bhi(u2.z) + bhi(u3.z));
    a[6] = (blo(u0.w) + blo(u1.w)) + (blo(u2.w) + blo(u3.w));
    a[7] = (bhi(u0.w) + bhi(u1.w)) + (bhi(u2.w) + bhi(u3.w));

    int slot = cs * 32 + (tid & 31);
#pragma unroll
    for (int i = 0; i < 8; i++) smQ[slot][i] = a[i];
    __syncthreads();

    // combine the 8 csplits in fixed order; coalesced fp32 out
    int lp = tid >> 3, e = tid & 7;
    float s = ((smQ[lp][e] + smQ[32 + lp][e])
             + (smQ[64 + lp][e] + smQ[96 + lp][e]))
            + ((smQ[128 + lp][e] + smQ[160 + lp][e])
             + (smQ[192 + lp][e] + smQ[224 + lp][e]));
    g_gsum[(size_t)gb * 16384 + (size_t)(blockIdx.x * 32 + lp) * 8 + e] = s;
}

// ===========================================================================
// k_redB: grid (FRB+1, 4), 256 thr. x<FRB: frobenius over fp32 g_gsum.
// x==FRB: s1. Last arriving block computes the final scalar loss.
// ===========================================================================
__global__ __launch_bounds__(256) void k_redB(float* __restrict__ out) {
    __shared__ float rr[8];
    __shared__ float sqs[DIM], sks[DIM];
    __shared__ bool last;
    int b = blockIdx.y;
    int tid = threadIdx.x;

    if (blockIdx.x < FRB) {
        int idx = blockIdx.x * 1024 + tid * 4;
        const float4* pq = (const float4*)(g_gsum + (size_t)(0 * BATCH + b) * 16384 + idx);
        const float4* pk = (const float4*)(g_gsum + (size_t)(1 * BATCH + b) * 16384 + idx);
        float4 gq = *pq;
        float4 gk = *pk;
        float f = (gq.x * gk.x + gq.y * gk.y) + (gq.z * gk.z + gq.w * gk.w);
#pragma unroll
        for (int o = 16; o; o >>= 1) f += __shfl_down_sync(0xffffffffu, f, o);
        if ((tid & 31) == 0) rr[tid >> 5] = f;
        __syncthreads();
        if (tid == 0) {
            float t = 0.f;
#pragma unroll
            for (int i = 0; i < 8; i++) t += rr[i];
            g_fpart[b * FRB + blockIdx.x] = t;
        }
    } else {
        int w = tid >> 7, d = tid & 127;
        const float* p = g_spart + ((size_t)(w * BATCH + b) * MC) * DIM + d;
        float s = 0.f;
#pragma unroll 8
        for (int c = 0; c < MC; c++) s += p[(size_t)c * DIM];
        if (w == 0) sqs[d] = s; else sks[d] = s;
        __syncthreads();
        if (tid < 128) {
            float v = sqs[tid] * sks[tid];
#pragma unroll
            for (int o = 16; o; o >>= 1) v += __shfl_down_sync(0xffffffffu, v, o);
            if ((tid & 31) == 0) rr[tid >> 5] = v;
        }
        __syncthreads();
        if (tid == 0) g_s1[b] = rr[0] + rr[1] + rr[2] + rr[3];
    }

    // ---- finisher: last of the (FRB+1)*BATCH blocks computes the loss -----
    __syncthreads();
    if (tid == 0) {
        __threadfence();
        last = (atomicAdd(&g_ctr, 1u) == (FRB + 1) * BATCH - 1);
    }
    __syncthreads();
    if (last) {
        __shared__ float red[256];
        const float halfT2 = 0.5f * INV_T * INV_T;
        float v = 0.f;
        if (tid < BATCH * FRB) v += (halfT2 / QS4) * g_fpart[tid];  // unscale 64^4
        if (tid < BATCH)       v += (INV_T / QS2) * g_s1[tid];      // unscale 64^2
        if (tid < NBLK)        v -= INV_T * g_dgpart[tid] + halfT2 * g_dg2part[tid];
        red[tid] = v;
        __syncthreads();
#pragma unroll
        for (int s = 128; s; s >>= 1) {
            if (tid < s) red[tid] += red[tid + s];
            __syncthreads();
        }
        if (tid == 0) {
            out[0] = logf((float)NPTS) + red[0] / ((float)NPTS * (float)NB);
            g_ctr = 0;   // reset for next graph replay
        }
    }
}

// ===========================================================================
extern "C" void kernel_launch(void* const* d_in, const int* in_sizes, int n_in,
                              void* d_out, int out_size) {
    const float* q = (const float*)d_in[0];
    const float* k = (const float*)d_in[1];
    float* out = (float*)d_out;
    (void)in_sizes; (void)n_in; (void)out_size;

    cudaFuncSetAttribute(k_main, cudaFuncAttributeMaxDynamicSharedMemorySize,
                         SB_TOTAL);

    k_main<<<dim3(MC, BATCH), 512, SB_TOTAL>>>(q, k);
    k_redA<<<dim3(64, 8), 256>>>();
    k_redB<<<dim3(FRB + 1, BATCH), 256>>>(out);
}